// round 3
// baseline (speedup 1.0000x reference)
#include <cuda_runtime.h>
#include <math.h>

#define NN 100000
#define DIM 128
#define NREL 12
#define NBASES 8
#define NEDGE 1000000
#define NP 400000
#define NHYP 20000
#define NB 64
#define LREL 64
#define LKV 128
#define LCTX 32
#define NHEAD 8
#define HDIM 16
#define EDGE_TILES 7830

// ---------------- device scratch ----------------
__device__ float g_W[NREL * DIM * DIM];
__device__ float g_kg[NN * DIM];
__device__ int   g_cnt[NN * NREL];
__device__ int   g_typeCnt[NREL];
__device__ int   g_typeOff[NREL + 1];
__device__ int   g_tileOff[NREL + 1];
__device__ int   g_cursor[NREL];
__device__ int   g_sorted[NEDGE];
__device__ float g_xt[NN * DIM];
__device__ int   g_bdegS[NHYP], g_bdegK[NHYP];
__device__ int   g_ddegS[NN], g_ddegK[NN];
__device__ float g_efS[NHYP * DIM], g_efK[NHYP * DIM];
__device__ int   g_flagS[NN], g_flagK[NN];
__device__ float g_noS[NN * DIM], g_noK[NN * DIM];
__device__ float g_related[NB * LKV * DIM];
__device__ float g_context[NB * LCTX * DIM];
__device__ float g_qh[NB * LCTX * DIM];
__device__ float g_kh[NB * LKV * DIM];
__device__ float g_vh[NB * LKV * DIM];
__device__ float g_o[NB * LCTX * DIM];
__device__ float g_attrel[NB * LCTX * DIM];
__device__ float g_t1[NB * LCTX * DIM];
__device__ float g_ucat[NB * 33 * DIM];
__device__ float g_t2[NB * 33 * DIM];
__device__ float g_his[NB * DIM];
__device__ float g_user[NB * DIM];

// ---------------- RGCN prep ----------------
__global__ void k_W(const float* __restrict__ bases, const float* __restrict__ comp) {
    int i = blockIdx.x * blockDim.x + threadIdx.x;
    if (i >= NREL * DIM * DIM) return;
    int r = i / (DIM * DIM), kn = i % (DIM * DIM);
    float s = 0.f;
#pragma unroll
    for (int b = 0; b < NBASES; b++)
        s = fmaf(comp[r * NBASES + b], bases[b * DIM * DIM + kn], s);
    g_W[i] = s;
}

__global__ void k_count(const int* __restrict__ dst, const int* __restrict__ ty) {
    int e = blockIdx.x * blockDim.x + threadIdx.x;
    if (e >= NEDGE) return;
    atomicAdd(&g_cnt[dst[e] * NREL + ty[e]], 1);
    atomicAdd(&g_typeCnt[ty[e]], 1);
}

__global__ void k_prefix() {
    int off = 0, toff = 0;
    for (int r = 0; r < NREL; r++) {
        g_typeOff[r] = off; g_cursor[r] = off; g_tileOff[r] = toff;
        int c = g_typeCnt[r];
        off += c; toff += (c + 127) >> 7;
    }
    g_typeOff[NREL] = off; g_tileOff[NREL] = toff;
}

__global__ void k_sort(const int* __restrict__ ty) {
    int e = blockIdx.x * blockDim.x + threadIdx.x;
    if (e >= NEDGE) return;
    g_sorted[atomicAdd(&g_cursor[ty[e]], 1)] = e;
}

// ------------- generic GEMM: C[M,128] = A[M,128] @ op(B) (+bias) -------------
__global__ void __launch_bounds__(256) k_gemm128(
    const float* __restrict__ A, const float* __restrict__ Bm,
    const float* __restrict__ bias, float* __restrict__ C, int M, int transB) {
    __shared__ float As[128][36];
    __shared__ float Bs[32][132];
    const int t = threadIdx.x, tx = t & 15, ty = t >> 4;
    const int m0 = blockIdx.x * 128;
    float acc[8][8];
#pragma unroll
    for (int i = 0; i < 8; i++)
#pragma unroll
        for (int j = 0; j < 8; j++) acc[i][j] = 0.f;
    const int mA = t >> 1, ksA = (t & 1) * 16;

    for (int k0 = 0; k0 < 128; k0 += 32) {
        int gm = m0 + mA;
        if (gm < M) {
            const float4* ap = reinterpret_cast<const float4*>(A + (size_t)gm * DIM + k0 + ksA);
#pragma unroll
            for (int q = 0; q < 4; q++) *reinterpret_cast<float4*>(&As[mA][ksA + 4 * q]) = ap[q];
        } else {
#pragma unroll
            for (int q = 0; q < 16; q++) As[mA][ksA + q] = 0.f;
        }
        if (!transB) {
            int kk = t >> 3, nc = (t & 7) * 16;
            const float4* bp = reinterpret_cast<const float4*>(Bm + (size_t)(k0 + kk) * DIM + nc);
#pragma unroll
            for (int q = 0; q < 4; q++) *reinterpret_cast<float4*>(&Bs[kk][nc + 4 * q]) = bp[q];
        } else {
            int n = t >> 1, ks = (t & 1) * 16;
            const float* bp = Bm + (size_t)n * DIM + k0 + ks;
#pragma unroll
            for (int q = 0; q < 16; q++) Bs[ks + q][n] = bp[q];
        }
        __syncthreads();
#pragma unroll
        for (int kk = 0; kk < 32; kk++) {
            float a[8], b[8];
#pragma unroll
            for (int i = 0; i < 8; i++) a[i] = As[ty * 8 + i][kk];
            float4 b0 = *reinterpret_cast<const float4*>(&Bs[kk][tx * 8]);
            float4 b1 = *reinterpret_cast<const float4*>(&Bs[kk][tx * 8 + 4]);
            b[0]=b0.x; b[1]=b0.y; b[2]=b0.z; b[3]=b0.w; b[4]=b1.x; b[5]=b1.y; b[6]=b1.z; b[7]=b1.w;
#pragma unroll
            for (int i = 0; i < 8; i++)
#pragma unroll
                for (int j = 0; j < 8; j++) acc[i][j] = fmaf(a[i], b[j], acc[i][j]);
        }
        __syncthreads();
    }
    float bb[8];
#pragma unroll
    for (int j = 0; j < 8; j++) bb[j] = bias ? bias[tx * 8 + j] : 0.f;
#pragma unroll
    for (int i = 0; i < 8; i++) {
        int gm = m0 + ty * 8 + i;
        if (gm < M) {
            float* cp = C + (size_t)gm * DIM + tx * 8;
#pragma unroll
            for (int j = 0; j < 8; j++) cp[j] = acc[i][j] + bb[j];
        }
    }
}

// ------------- RGCN edge GEMM: kg[dst] += norm * x[src] @ W[type] -------------
__global__ void __launch_bounds__(256) k_edge_gemm(
    const float* __restrict__ X, const int* __restrict__ esrc, const int* __restrict__ edst) {
    __shared__ float As[128][36];
    __shared__ float Bs[32][132];
    __shared__ int   sSrc[128], sDst[128];
    __shared__ float sNorm[128];
    const int bid = blockIdx.x;
    if (bid >= g_tileOff[NREL]) return;
    int r = 0;
    while (bid >= g_tileOff[r + 1]) r++;
    const int base = g_typeOff[r] + (bid - g_tileOff[r]) * 128;
    int cnt = g_typeOff[r + 1] - base;
    if (cnt > 128) cnt = 128;
    const int t = threadIdx.x, tx = t & 15, ty = t >> 4;
    if (t < 128) {
        if (t < cnt) {
            int e = g_sorted[base + t];
            int d = edst[e];
            sSrc[t] = esrc[e]; sDst[t] = d;
            sNorm[t] = 1.0f / fmaxf((float)g_cnt[d * NREL + r], 1.0f);
        } else { sSrc[t] = 0; sDst[t] = -1; sNorm[t] = 0.f; }
    }
    __syncthreads();
    float acc[8][8];
#pragma unroll
    for (int i = 0; i < 8; i++)
#pragma unroll
        for (int j = 0; j < 8; j++) acc[i][j] = 0.f;
    const int mA = t >> 1, ksA = (t & 1) * 16;
    const float* Wr = g_W + (size_t)r * DIM * DIM;

    for (int k0 = 0; k0 < 128; k0 += 32) {
        {
            float nrm = sNorm[mA];
            const float4* ap = reinterpret_cast<const float4*>(X + (size_t)sSrc[mA] * DIM + k0 + ksA);
#pragma unroll
            for (int q = 0; q < 4; q++) {
                float4 v = ap[q];
                v.x *= nrm; v.y *= nrm; v.z *= nrm; v.w *= nrm;
                *reinterpret_cast<float4*>(&As[mA][ksA + 4 * q]) = v;
            }
        }
        {
            int kk = t >> 3, nc = (t & 7) * 16;
            const float4* bp = reinterpret_cast<const float4*>(Wr + (size_t)(k0 + kk) * DIM + nc);
#pragma unroll
            for (int q = 0; q < 4; q++) *reinterpret_cast<float4*>(&Bs[kk][nc + 4 * q]) = bp[q];
        }
        __syncthreads();
#pragma unroll
        for (int kk = 0; kk < 32; kk++) {
            float a[8], b[8];
#pragma unroll
            for (int i = 0; i < 8; i++) a[i] = As[ty * 8 + i][kk];
            float4 b0 = *reinterpret_cast<const float4*>(&Bs[kk][tx * 8]);
            float4 b1 = *reinterpret_cast<const float4*>(&Bs[kk][tx * 8 + 4]);
            b[0]=b0.x; b[1]=b0.y; b[2]=b0.z; b[3]=b0.w; b[4]=b1.x; b[5]=b1.y; b[6]=b1.z; b[7]=b1.w;
#pragma unroll
            for (int i = 0; i < 8; i++)
#pragma unroll
                for (int j = 0; j < 8; j++) acc[i][j] = fmaf(a[i], b[j], acc[i][j]);
        }
        __syncthreads();
    }
#pragma unroll
    for (int i = 0; i < 8; i++) {
        int dn = sDst[ty * 8 + i];
        if (dn >= 0) {
            float* op = g_kg + (size_t)dn * DIM + tx * 8;
#pragma unroll
            for (int j = 0; j < 8; j++) atomicAdd(op + j, acc[i][j]);
        }
    }
}

// ---------------- hypergraph ----------------
__global__ void k_hyper_count(const int* __restrict__ nodes, const int* __restrict__ edges,
                              int* __restrict__ bdeg, int* __restrict__ ddeg) {
    int p = blockIdx.x * blockDim.x + threadIdx.x;
    if (p >= NP) return;
    atomicAdd(&bdeg[edges[p]], 1);
    atomicAdd(&ddeg[nodes[p]], 1);
}

__global__ void k_scatter_ef(const int* __restrict__ nodes, const int* __restrict__ edges,
                             float* __restrict__ ef) {
    int w = (blockIdx.x * blockDim.x + threadIdx.x) >> 5;
    int lane = threadIdx.x & 31;
    if (w >= NP) return;
    float4 v = *reinterpret_cast<const float4*>(&g_xt[(size_t)nodes[w] * DIM + lane * 4]);
    float* dp = ef + (size_t)edges[w] * DIM + lane * 4;
    atomicAdd(dp, v.x); atomicAdd(dp + 1, v.y); atomicAdd(dp + 2, v.z); atomicAdd(dp + 3, v.w);
}

__global__ void k_scale_ef(float* __restrict__ ef, const int* __restrict__ bdeg) {
    int i = blockIdx.x * blockDim.x + threadIdx.x;
    if (i >= NHYP * DIM) return;
    int d = bdeg[i >> 7];
    ef[i] *= (d > 0) ? (1.0f / (float)d) : 0.0f;
}

__global__ void k_flag(const int* __restrict__ idx, int* __restrict__ flag, float* __restrict__ no) {
    int i = blockIdx.x * blockDim.x + threadIdx.x;
    if (i >= NB * LREL) return;
    int n = idx[i];
    flag[n] = 1;
    float* p = no + (size_t)n * DIM;
    for (int d = 0; d < DIM; d++) p[d] = 0.f;
}

__global__ void k_scatter_node(const int* __restrict__ nodes, const int* __restrict__ edges,
                               const int* __restrict__ flag, const float* __restrict__ ef,
                               float* __restrict__ no) {
    int w = (blockIdx.x * blockDim.x + threadIdx.x) >> 5;
    int lane = threadIdx.x & 31;
    if (w >= NP) return;
    int n = nodes[w];
    if (!flag[n]) return;
    float4 v = *reinterpret_cast<const float4*>(ef + (size_t)edges[w] * DIM + lane * 4);
    float* dp = no + (size_t)n * DIM + lane * 4;
    atomicAdd(dp, v.x); atomicAdd(dp + 1, v.y); atomicAdd(dp + 2, v.z); atomicAdd(dp + 3, v.w);
}

__global__ void k_gather_rel(const int* __restrict__ sidx, const int* __restrict__ kidx,
                             const float* __restrict__ biasS, const float* __restrict__ biasK) {
    int i = blockIdx.x * blockDim.x + threadIdx.x;
    if (i >= NB * LKV * DIM) return;
    int d = i & 127, l = (i >> 7) & 127, b = i >> 14;
    float v;
    if (l < LREL) {
        int n = sidx[b * LREL + l]; int dd = g_ddegS[n];
        v = g_noS[(size_t)n * DIM + d] * (dd > 0 ? 1.f / dd : 0.f) + biasS[d];
    } else {
        int n = kidx[b * LREL + l - LREL]; int dd = g_ddegK[n];
        v = g_noK[(size_t)n * DIM + d] * (dd > 0 ? 1.f / dd : 0.f) + biasK[d];
    }
    g_related[i] = v;
}

__global__ void k_gather_ctx(const int* __restrict__ idx) {
    int i = blockIdx.x * blockDim.x + threadIdx.x;
    if (i >= NB * LCTX * DIM) return;
    g_context[i] = g_kg[(size_t)idx[i >> 7] * DIM + (i & 127)];
}

// ---------------- attention ----------------
__global__ void k_mha() {
    int b = blockIdx.x / NHEAD, h = blockIdx.x % NHEAD;
    __shared__ float ks[LKV][HDIM], vs[LKV][HDIM];
    int t = threadIdx.x;
    for (int i = t; i < LKV * HDIM; i += 32) {
        int k = i / HDIM, d = i % HDIM;
        size_t off = ((size_t)b * LKV + k) * DIM + h * HDIM + d;
        ks[k][d] = g_kh[off]; vs[k][d] = g_vh[off];
    }
    __syncwarp();
    float q[HDIM];
    size_t qoff = ((size_t)b * LCTX + t) * DIM + h * HDIM;
#pragma unroll
    for (int d = 0; d < HDIM; d++) q[d] = g_qh[qoff + d];
    float lg[LKV], mx = -1e30f;
    for (int k = 0; k < LKV; k++) {
        float s = 0.f;
#pragma unroll
        for (int d = 0; d < HDIM; d++) s += q[d] * ks[k][d];
        s *= 0.25f; lg[k] = s; mx = fmaxf(mx, s);
    }
    float sum = 0.f;
    for (int k = 0; k < LKV; k++) { lg[k] = expf(lg[k] - mx); sum += lg[k]; }
    float inv = 1.f / sum;
    float acc[HDIM];
#pragma unroll
    for (int d = 0; d < HDIM; d++) acc[d] = 0.f;
    for (int k = 0; k < LKV; k++) {
        float w = lg[k];
#pragma unroll
        for (int d = 0; d < HDIM; d++) acc[d] += w * vs[k][d];
    }
#pragma unroll
    for (int d = 0; d < HDIM; d++) g_o[qoff + d] = acc[d] * inv;
}

__global__ void k_selfattn(const float* __restrict__ h, const float* __restrict__ t1,
                           const float* __restrict__ bvec, float* __restrict__ out, int L) {
    int b = blockIdx.x, t = threadIdx.x;
    __shared__ float w[40];
    if (t < L) {
        float e = 0.f;
        const float* tp = t1 + ((size_t)b * L + t) * DIM;
        for (int d = 0; d < DIM; d++) e += tanhf(tp[d]) * bvec[d];
        w[t] = e;
    }
    __syncthreads();
    float mx = -1e30f;
    for (int l = 0; l < L; l++) mx = fmaxf(mx, w[l]);
    float sum = 0.f;
    for (int l = 0; l < L; l++) sum += expf(w[l] - mx);
    float inv = 1.f / sum, acc = 0.f;
    for (int l = 0; l < L; l++) acc += expf(w[l] - mx) * h[((size_t)b * L + l) * DIM + t];
    out[(size_t)b * DIM + t] = acc * inv;
}

__global__ void k_ucat() {
    int i = blockIdx.x * blockDim.x + threadIdx.x;
    if (i >= NB * 33 * DIM) return;
    int d = i & 127, l = (i >> 7) % 33, b = i / (33 * DIM);
    g_ucat[i] = (l < 32) ? g_context[((size_t)b * 32 + l) * DIM + d] : g_his[(size_t)b * DIM + d];
}

__global__ void k_scores(const float* __restrict__ rb, float* __restrict__ out) {
    __shared__ float su[32][DIM];
    int t = threadIdx.x;
    int u0 = blockIdx.y * 32;
    for (int i = t; i < 32 * DIM; i += 128)
        su[i >> 7][i & 127] = g_user[(size_t)(u0 + (i >> 7)) * DIM + (i & 127)];
    __syncthreads();
    int n = blockIdx.x * 128 + t;
    if (n >= NN) return;
    float acc[32];
#pragma unroll
    for (int u = 0; u < 32; u++) acc[u] = 0.f;
    const float4* kr = reinterpret_cast<const float4*>(g_kg + (size_t)n * DIM);
    for (int kc = 0; kc < DIM / 4; kc++) {
        float4 v = kr[kc];
#pragma unroll
        for (int u = 0; u < 32; u++)
            acc[u] += su[u][kc*4]*v.x + su[u][kc*4+1]*v.y + su[u][kc*4+2]*v.z + su[u][kc*4+3]*v.w;
    }
    float b = rb[n];
    for (int u = 0; u < 32; u++) out[(size_t)(u0 + u) * NN + n] = acc[u] + b;
}

// ---------------- host ----------------
static void* sym(const void* s) { void* p = nullptr; cudaGetSymbolAddress(&p, s); return p; }

extern "C" void kernel_launch(void* const* d_in, const int* in_sizes, int n_in,
                              void* d_out, int out_size) {
    const float* emb   = (const float*)d_in[0];
    const float* bases = (const float*)d_in[1];
    const float* comp  = (const float*)d_in[2];
    const float* root  = (const float*)d_in[3];
    const float* rbias = (const float*)d_in[4];
    const float* sth   = (const float*)d_in[5];
    const float* sbi   = (const float*)d_in[6];
    const float* kth   = (const float*)d_in[7];
    const float* kbi   = (const float*)d_in[8];
    const float* ipw   = (const float*)d_in[9];
    const float* ipb   = (const float*)d_in[10];
    const float* opw   = (const float*)d_in[11];
    const float* opb   = (const float*)d_in[12];
    const float* aha   = (const float*)d_in[13];
    const float* ahb   = (const float*)d_in[14];
    const float* aa    = (const float*)d_in[15];
    const float* ab    = (const float*)d_in[16];
    const float* recb  = (const float*)d_in[17];
    const int* esrc = (const int*)d_in[18];
    const int* edst = (const int*)d_in[19];
    const int* ety  = (const int*)d_in[20];
    const int* snod = (const int*)d_in[21];
    const int* sedg = (const int*)d_in[22];
    const int* knod = (const int*)d_in[23];
    const int* kedg = (const int*)d_in[24];
    const int* sri  = (const int*)d_in[25];
    const int* kri  = (const int*)d_in[26];
    const int* cxi  = (const int*)d_in[27];
    float* out = (float*)d_out;

    cudaMemsetAsync(sym(g_cnt), 0, (size_t)NN * NREL * 4, 0);
    cudaMemsetAsync(sym(g_typeCnt), 0, NREL * 4, 0);
    cudaMemsetAsync(sym(g_bdegS), 0, NHYP * 4, 0);
    cudaMemsetAsync(sym(g_bdegK), 0, NHYP * 4, 0);
    cudaMemsetAsync(sym(g_ddegS), 0, (size_t)NN * 4, 0);
    cudaMemsetAsync(sym(g_ddegK), 0, (size_t)NN * 4, 0);
    cudaMemsetAsync(sym(g_efS), 0, (size_t)NHYP * DIM * 4, 0);
    cudaMemsetAsync(sym(g_efK), 0, (size_t)NHYP * DIM * 4, 0);
    cudaMemsetAsync(sym(g_flagS), 0, (size_t)NN * 4, 0);
    cudaMemsetAsync(sym(g_flagK), 0, (size_t)NN * 4, 0);

    float* kg  = (float*)sym(g_kg);
    float* xt  = (float*)sym(g_xt);

    k_W<<<(NREL * DIM * DIM + 255) / 256, 256>>>(bases, comp);
    k_count<<<(NEDGE + 255) / 256, 256>>>(edst, ety);
    k_prefix<<<1, 1>>>();
    k_sort<<<(NEDGE + 255) / 256, 256>>>(ety);

    k_gemm128<<<(NN + 127) / 128, 256>>>(emb, root, rbias, kg, NN, 0);
    k_edge_gemm<<<EDGE_TILES, 256>>>(emb, esrc, edst);

    // sess hypergraph
    k_gemm128<<<(NN + 127) / 128, 256>>>(kg, sth, nullptr, xt, NN, 0);
    k_hyper_count<<<(NP + 255) / 256, 256>>>(snod, sedg, (int*)sym(g_bdegS), (int*)sym(g_ddegS));
    k_scatter_ef<<<(NP * 32 + 255) / 256, 256>>>(snod, sedg, (float*)sym(g_efS));
    k_scale_ef<<<(NHYP * DIM + 255) / 256, 256>>>((float*)sym(g_efS), (int*)sym(g_bdegS));
    k_flag<<<(NB * LREL + 255) / 256, 256>>>(sri, (int*)sym(g_flagS), (float*)sym(g_noS));
    k_scatter_node<<<(NP * 32 + 255) / 256, 256>>>(snod, sedg, (int*)sym(g_flagS),
                                                   (float*)sym(g_efS), (float*)sym(g_noS));
    // know hypergraph
    k_gemm128<<<(NN + 127) / 128, 256>>>(kg, kth, nullptr, xt, NN, 0);
    k_hyper_count<<<(NP + 255) / 256, 256>>>(knod, kedg, (int*)sym(g_bdegK), (int*)sym(g_ddegK));
    k_scatter_ef<<<(NP * 32 + 255) / 256, 256>>>(knod, kedg, (float*)sym(g_efK));
    k_scale_ef<<<(NHYP * DIM + 255) / 256, 256>>>((float*)sym(g_efK), (int*)sym(g_bdegK));
    k_flag<<<(NB * LREL + 255) / 256, 256>>>(kri, (int*)sym(g_flagK), (float*)sym(g_noK));
    k_scatter_node<<<(NP * 32 + 255) / 256, 256>>>(knod, kedg, (int*)sym(g_flagK),
                                                   (float*)sym(g_efK), (float*)sym(g_noK));

    k_gather_rel<<<(NB * LKV * DIM + 255) / 256, 256>>>(sri, kri, sbi, kbi);
    k_gather_ctx<<<(NB * LCTX * DIM + 255) / 256, 256>>>(cxi);

    // MHA projections
    float* ctx = (float*)sym(g_context);
    float* rel = (float*)sym(g_related);
    k_gemm128<<<(NB * LCTX + 127) / 128, 256>>>(ctx, ipw, ipb, (float*)sym(g_qh), NB * LCTX, 1);
    k_gemm128<<<(NB * LKV + 127) / 128, 256>>>(rel, ipw + DIM * DIM, ipb + DIM,
                                               (float*)sym(g_kh), NB * LKV, 1);
    k_gemm128<<<(NB * LKV + 127) / 128, 256>>>(rel, ipw + 2 * DIM * DIM, ipb + 2 * DIM,
                                               (float*)sym(g_vh), NB * LKV, 1);
    k_mha<<<NB * NHEAD, 32>>>();
    k_gemm128<<<(NB * LCTX + 127) / 128, 256>>>((float*)sym(g_o), opw, opb,
                                                (float*)sym(g_attrel), NB * LCTX, 1);

    // his self-attn
    k_gemm128<<<(NB * LCTX + 127) / 128, 256>>>((float*)sym(g_attrel), aha, nullptr,
                                                (float*)sym(g_t1), NB * LCTX, 0);
    k_selfattn<<<NB, 128>>>((float*)sym(g_attrel), (float*)sym(g_t1), ahb,
                            (float*)sym(g_his), LCTX);

    // user self-attn over [context, his]
    k_ucat<<<(NB * 33 * DIM + 255) / 256, 256>>>();
    k_gemm128<<<(NB * 33 + 127) / 128, 256>>>((float*)sym(g_ucat), aa, nullptr,
                                              (float*)sym(g_t2), NB * 33, 0);
    k_selfattn<<<NB, 128>>>((float*)sym(g_ucat), (float*)sym(g_t2), ab,
                            (float*)sym(g_user), 33);

    // scores
    dim3 sg((NN + 127) / 128, 2);
    k_scores<<<sg, 128>>>(recb, out);
}

// round 4
// speedup vs baseline: 1.2528x; 1.2528x over previous
#include <cuda_runtime.h>
#include <math.h>

#define NN 100000
#define DIM 128
#define NREL 12
#define NBASES 8
#define NEDGE 1000000
#define NP 400000
#define NHYP 20000
#define NB 64
#define LREL 64
#define LKV 128
#define LCTX 32
#define NHEAD 8
#define HDIM 16
#define EDGE_TILES 7830

__device__ __forceinline__ void red_add_v4(float* p, float x, float y, float z, float w) {
    asm volatile("red.global.add.v4.f32 [%0], {%1,%2,%3,%4};"
                 :: "l"(p), "f"(x), "f"(y), "f"(z), "f"(w) : "memory");
}

// ---------------- device scratch ----------------
__device__ float g_W[NREL * DIM * DIM];
__device__ float g_kg[NN * DIM];
__device__ int   g_cnt[NN * NREL];
__device__ int   g_typeCnt[NREL];
__device__ int   g_typeOff[NREL + 1];
__device__ int   g_tileOff[NREL + 1];
__device__ int   g_cursor[NREL];
__device__ int   g_sorted[NEDGE];
__device__ float g_xt[NN * DIM];
__device__ int   g_bdegS[NHYP], g_bdegK[NHYP];
__device__ int   g_ddegS[NN], g_ddegK[NN];
__device__ float g_efS[NHYP * DIM], g_efK[NHYP * DIM];
__device__ int   g_flagS[NN], g_flagK[NN];
__device__ float g_noS[NN * DIM], g_noK[NN * DIM];
__device__ float g_related[NB * LKV * DIM];
__device__ float g_context[NB * LCTX * DIM];
__device__ float g_qh[NB * LCTX * DIM];
__device__ float g_kh[NB * LKV * DIM];
__device__ float g_vh[NB * LKV * DIM];
__device__ float g_o[NB * LCTX * DIM];
__device__ float g_attrel[NB * LCTX * DIM];
__device__ float g_t1[NB * LCTX * DIM];
__device__ float g_ucat[NB * 33 * DIM];
__device__ float g_t2[NB * 33 * DIM];
__device__ float g_his[NB * DIM];
__device__ float g_user[NB * DIM];

// ---------------- RGCN prep ----------------
__global__ void k_W(const float* __restrict__ bases, const float* __restrict__ comp) {
    int i = blockIdx.x * blockDim.x + threadIdx.x;
    if (i >= NREL * DIM * DIM) return;
    int r = i / (DIM * DIM), kn = i % (DIM * DIM);
    float s = 0.f;
#pragma unroll
    for (int b = 0; b < NBASES; b++)
        s = fmaf(comp[r * NBASES + b], bases[b * DIM * DIM + kn], s);
    g_W[i] = s;
}

// block-aggregated type histogram + per-(dst,type) counts
__global__ void k_count(const int* __restrict__ dst, const int* __restrict__ ty) {
    __shared__ int h[NREL];
    int t = threadIdx.x;
    if (t < NREL) h[t] = 0;
    __syncthreads();
    int e = blockIdx.x * blockDim.x + t;
    if (e < NEDGE) {
        int tt = ty[e];
        atomicAdd(&g_cnt[dst[e] * NREL + tt], 1);
        atomicAdd(&h[tt], 1);
    }
    __syncthreads();
    if (t < NREL && h[t]) atomicAdd(&g_typeCnt[t], h[t]);
}

__global__ void k_prefix() {
    int off = 0, toff = 0;
    for (int r = 0; r < NREL; r++) {
        g_typeOff[r] = off; g_cursor[r] = off; g_tileOff[r] = toff;
        int c = g_typeCnt[r];
        off += c; toff += (c + 127) >> 7;
    }
    g_typeOff[NREL] = off; g_tileOff[NREL] = toff;
}

// block-aggregated counting sort: shared hist -> one global reservation per type
__global__ void k_sort(const int* __restrict__ ty) {
    __shared__ int h[NREL], base[NREL];
    int t = threadIdx.x;
    if (t < NREL) h[t] = 0;
    __syncthreads();
    int e = blockIdx.x * blockDim.x + t;
    int tt = -1, loc = 0;
    if (e < NEDGE) { tt = ty[e]; loc = atomicAdd(&h[tt], 1); }
    __syncthreads();
    if (t < NREL) base[t] = h[t] ? atomicAdd(&g_cursor[t], h[t]) : 0;
    __syncthreads();
    if (e < NEDGE) g_sorted[base[tt] + loc] = e;
}

// ------------- generic GEMM: C[M,128] = A[M,128] @ op(B) (+bias) -------------
__global__ void __launch_bounds__(256) k_gemm128(
    const float* __restrict__ A, const float* __restrict__ Bm,
    const float* __restrict__ bias, float* __restrict__ C, int M, int transB) {
    __shared__ float As[128][36];
    __shared__ float Bs[32][132];
    const int t = threadIdx.x, tx = t & 15, ty = t >> 4;
    const int m0 = blockIdx.x * 128;
    float acc[8][8];
#pragma unroll
    for (int i = 0; i < 8; i++)
#pragma unroll
        for (int j = 0; j < 8; j++) acc[i][j] = 0.f;
    const int mA = t >> 1, ksA = (t & 1) * 16;

    for (int k0 = 0; k0 < 128; k0 += 32) {
        int gm = m0 + mA;
        if (gm < M) {
            const float4* ap = reinterpret_cast<const float4*>(A + (size_t)gm * DIM + k0 + ksA);
#pragma unroll
            for (int q = 0; q < 4; q++) *reinterpret_cast<float4*>(&As[mA][ksA + 4 * q]) = ap[q];
        } else {
#pragma unroll
            for (int q = 0; q < 16; q++) As[mA][ksA + q] = 0.f;
        }
        if (!transB) {
            int kk = t >> 3, nc = (t & 7) * 16;
            const float4* bp = reinterpret_cast<const float4*>(Bm + (size_t)(k0 + kk) * DIM + nc);
#pragma unroll
            for (int q = 0; q < 4; q++) *reinterpret_cast<float4*>(&Bs[kk][nc + 4 * q]) = bp[q];
        } else {
            int n = t >> 1, ks = (t & 1) * 16;
            const float* bp = Bm + (size_t)n * DIM + k0 + ks;
#pragma unroll
            for (int q = 0; q < 16; q++) Bs[ks + q][n] = bp[q];
        }
        __syncthreads();
#pragma unroll
        for (int kk = 0; kk < 32; kk++) {
            float a[8], b[8];
#pragma unroll
            for (int i = 0; i < 8; i++) a[i] = As[ty * 8 + i][kk];
            float4 b0 = *reinterpret_cast<const float4*>(&Bs[kk][tx * 8]);
            float4 b1 = *reinterpret_cast<const float4*>(&Bs[kk][tx * 8 + 4]);
            b[0]=b0.x; b[1]=b0.y; b[2]=b0.z; b[3]=b0.w; b[4]=b1.x; b[5]=b1.y; b[6]=b1.z; b[7]=b1.w;
#pragma unroll
            for (int i = 0; i < 8; i++)
#pragma unroll
                for (int j = 0; j < 8; j++) acc[i][j] = fmaf(a[i], b[j], acc[i][j]);
        }
        __syncthreads();
    }
    float bb[8];
#pragma unroll
    for (int j = 0; j < 8; j++) bb[j] = bias ? bias[tx * 8 + j] : 0.f;
#pragma unroll
    for (int i = 0; i < 8; i++) {
        int gm = m0 + ty * 8 + i;
        if (gm < M) {
            float* cp = C + (size_t)gm * DIM + tx * 8;
#pragma unroll
            for (int j = 0; j < 8; j++) cp[j] = acc[i][j] + bb[j];
        }
    }
}

// ------------- RGCN edge GEMM: kg[dst] += norm * x[src] @ W[type] -------------
__global__ void __launch_bounds__(256) k_edge_gemm(
    const float* __restrict__ X, const int* __restrict__ esrc, const int* __restrict__ edst) {
    __shared__ float As[128][36];
    __shared__ float Bs[32][132];
    __shared__ int   sSrc[128], sDst[128];
    __shared__ float sNorm[128];
    const int bid = blockIdx.x;
    if (bid >= g_tileOff[NREL]) return;
    int r = 0;
    while (bid >= g_tileOff[r + 1]) r++;
    const int base = g_typeOff[r] + (bid - g_tileOff[r]) * 128;
    int cnt = g_typeOff[r + 1] - base;
    if (cnt > 128) cnt = 128;
    const int t = threadIdx.x, tx = t & 15, ty = t >> 4;
    if (t < 128) {
        if (t < cnt) {
            int e = g_sorted[base + t];
            int d = edst[e];
            sSrc[t] = esrc[e]; sDst[t] = d;
            sNorm[t] = 1.0f / fmaxf((float)g_cnt[d * NREL + r], 1.0f);
        } else { sSrc[t] = 0; sDst[t] = -1; sNorm[t] = 0.f; }
    }
    __syncthreads();
    float acc[8][8];
#pragma unroll
    for (int i = 0; i < 8; i++)
#pragma unroll
        for (int j = 0; j < 8; j++) acc[i][j] = 0.f;
    const int mA = t >> 1, ksA = (t & 1) * 16;
    const float* Wr = g_W + (size_t)r * DIM * DIM;

    for (int k0 = 0; k0 < 128; k0 += 32) {
        {
            float nrm = sNorm[mA];
            const float4* ap = reinterpret_cast<const float4*>(X + (size_t)sSrc[mA] * DIM + k0 + ksA);
#pragma unroll
            for (int q = 0; q < 4; q++) {
                float4 v = ap[q];
                v.x *= nrm; v.y *= nrm; v.z *= nrm; v.w *= nrm;
                *reinterpret_cast<float4*>(&As[mA][ksA + 4 * q]) = v;
            }
        }
        {
            int kk = t >> 3, nc = (t & 7) * 16;
            const float4* bp = reinterpret_cast<const float4*>(Wr + (size_t)(k0 + kk) * DIM + nc);
#pragma unroll
            for (int q = 0; q < 4; q++) *reinterpret_cast<float4*>(&Bs[kk][nc + 4 * q]) = bp[q];
        }
        __syncthreads();
#pragma unroll
        for (int kk = 0; kk < 32; kk++) {
            float a[8], b[8];
#pragma unroll
            for (int i = 0; i < 8; i++) a[i] = As[ty * 8 + i][kk];
            float4 b0 = *reinterpret_cast<const float4*>(&Bs[kk][tx * 8]);
            float4 b1 = *reinterpret_cast<const float4*>(&Bs[kk][tx * 8 + 4]);
            b[0]=b0.x; b[1]=b0.y; b[2]=b0.z; b[3]=b0.w; b[4]=b1.x; b[5]=b1.y; b[6]=b1.z; b[7]=b1.w;
#pragma unroll
            for (int i = 0; i < 8; i++)
#pragma unroll
                for (int j = 0; j < 8; j++) acc[i][j] = fmaf(a[i], b[j], acc[i][j]);
        }
        __syncthreads();
    }
#pragma unroll
    for (int i = 0; i < 8; i++) {
        int dn = sDst[ty * 8 + i];
        if (dn >= 0) {
            float* op = g_kg + (size_t)dn * DIM + tx * 8;
            red_add_v4(op,     acc[i][0], acc[i][1], acc[i][2], acc[i][3]);
            red_add_v4(op + 4, acc[i][4], acc[i][5], acc[i][6], acc[i][7]);
        }
    }
}

// ---------------- hypergraph ----------------
__global__ void k_hyper_count(const int* __restrict__ nodes, const int* __restrict__ edges,
                              int* __restrict__ bdeg, int* __restrict__ ddeg) {
    int p = blockIdx.x * blockDim.x + threadIdx.x;
    if (p >= NP) return;
    atomicAdd(&bdeg[edges[p]], 1);
    atomicAdd(&ddeg[nodes[p]], 1);
}

__global__ void k_scatter_ef(const int* __restrict__ nodes, const int* __restrict__ edges,
                             float* __restrict__ ef) {
    int w = (blockIdx.x * blockDim.x + threadIdx.x) >> 5;
    int lane = threadIdx.x & 31;
    if (w >= NP) return;
    float4 v = *reinterpret_cast<const float4*>(&g_xt[(size_t)nodes[w] * DIM + lane * 4]);
    red_add_v4(ef + (size_t)edges[w] * DIM + lane * 4, v.x, v.y, v.z, v.w);
}

__global__ void k_flag(const int* __restrict__ idx, int* __restrict__ flag, float* __restrict__ no) {
    int i = blockIdx.x * blockDim.x + threadIdx.x;
    if (i >= NB * LREL) return;
    int n = idx[i];
    flag[n] = 1;
    float* p = no + (size_t)n * DIM;
    for (int d = 0; d < DIM; d++) p[d] = 0.f;
}

// node scatter with 1/b_deg folded in at read time
__global__ void k_scatter_node(const int* __restrict__ nodes, const int* __restrict__ edges,
                               const int* __restrict__ flag, const float* __restrict__ ef,
                               const int* __restrict__ bdeg, float* __restrict__ no) {
    int w = (blockIdx.x * blockDim.x + threadIdx.x) >> 5;
    int lane = threadIdx.x & 31;
    if (w >= NP) return;
    int n = nodes[w];
    if (!flag[n]) return;
    int he = edges[w];
    int d = bdeg[he];
    float inv = (d > 0) ? (1.0f / (float)d) : 0.0f;
    float4 v = *reinterpret_cast<const float4*>(ef + (size_t)he * DIM + lane * 4);
    red_add_v4(no + (size_t)n * DIM + lane * 4, v.x * inv, v.y * inv, v.z * inv, v.w * inv);
}

__global__ void k_gather_rel(const int* __restrict__ sidx, const int* __restrict__ kidx,
                             const float* __restrict__ biasS, const float* __restrict__ biasK) {
    int i = blockIdx.x * blockDim.x + threadIdx.x;
    if (i >= NB * LKV * DIM) return;
    int d = i & 127, l = (i >> 7) & 127, b = i >> 14;
    float v;
    if (l < LREL) {
        int n = sidx[b * LREL + l]; int dd = g_ddegS[n];
        v = g_noS[(size_t)n * DIM + d] * (dd > 0 ? 1.f / dd : 0.f) + biasS[d];
    } else {
        int n = kidx[b * LREL + l - LREL]; int dd = g_ddegK[n];
        v = g_noK[(size_t)n * DIM + d] * (dd > 0 ? 1.f / dd : 0.f) + biasK[d];
    }
    g_related[i] = v;
}

__global__ void k_gather_ctx(const int* __restrict__ idx) {
    int i = blockIdx.x * blockDim.x + threadIdx.x;
    if (i >= NB * LCTX * DIM) return;
    g_context[i] = g_kg[(size_t)idx[i >> 7] * DIM + (i & 127)];
}

// ---------------- attention ----------------
__global__ void k_mha() {
    int b = blockIdx.x / NHEAD, h = blockIdx.x % NHEAD;
    __shared__ float ks[LKV][HDIM], vs[LKV][HDIM];
    int t = threadIdx.x;
    for (int i = t; i < LKV * HDIM; i += 32) {
        int k = i / HDIM, d = i % HDIM;
        size_t off = ((size_t)b * LKV + k) * DIM + h * HDIM + d;
        ks[k][d] = g_kh[off]; vs[k][d] = g_vh[off];
    }
    __syncwarp();
    float q[HDIM];
    size_t qoff = ((size_t)b * LCTX + t) * DIM + h * HDIM;
#pragma unroll
    for (int d = 0; d < HDIM; d++) q[d] = g_qh[qoff + d];
    float lg[LKV], mx = -1e30f;
    for (int k = 0; k < LKV; k++) {
        float s = 0.f;
#pragma unroll
        for (int d = 0; d < HDIM; d++) s += q[d] * ks[k][d];
        s *= 0.25f; lg[k] = s; mx = fmaxf(mx, s);
    }
    float sum = 0.f;
    for (int k = 0; k < LKV; k++) { lg[k] = expf(lg[k] - mx); sum += lg[k]; }
    float inv = 1.f / sum;
    float acc[HDIM];
#pragma unroll
    for (int d = 0; d < HDIM; d++) acc[d] = 0.f;
    for (int k = 0; k < LKV; k++) {
        float w = lg[k];
#pragma unroll
        for (int d = 0; d < HDIM; d++) acc[d] += w * vs[k][d];
    }
#pragma unroll
    for (int d = 0; d < HDIM; d++) g_o[qoff + d] = acc[d] * inv;
}

__global__ void k_selfattn(const float* __restrict__ h, const float* __restrict__ t1,
                           const float* __restrict__ bvec, float* __restrict__ out, int L) {
    int b = blockIdx.x, t = threadIdx.x;
    __shared__ float w[40];
    if (t < L) {
        float e = 0.f;
        const float* tp = t1 + ((size_t)b * L + t) * DIM;
        for (int d = 0; d < DIM; d++) e += tanhf(tp[d]) * bvec[d];
        w[t] = e;
    }
    __syncthreads();
    float mx = -1e30f;
    for (int l = 0; l < L; l++) mx = fmaxf(mx, w[l]);
    float sum = 0.f;
    for (int l = 0; l < L; l++) sum += expf(w[l] - mx);
    float inv = 1.f / sum, acc = 0.f;
    for (int l = 0; l < L; l++) acc += expf(w[l] - mx) * h[((size_t)b * L + l) * DIM + t];
    out[(size_t)b * DIM + t] = acc * inv;
}

__global__ void k_ucat() {
    int i = blockIdx.x * blockDim.x + threadIdx.x;
    if (i >= NB * 33 * DIM) return;
    int d = i & 127, l = (i >> 7) % 33, b = i / (33 * DIM);
    g_ucat[i] = (l < 32) ? g_context[((size_t)b * 32 + l) * DIM + d] : g_his[(size_t)b * DIM + d];
}

__global__ void k_scores(const float* __restrict__ rb, float* __restrict__ out) {
    __shared__ float su[32][DIM];
    int t = threadIdx.x;
    int u0 = blockIdx.y * 32;
    for (int i = t; i < 32 * DIM; i += 128)
        su[i >> 7][i & 127] = g_user[(size_t)(u0 + (i >> 7)) * DIM + (i & 127)];
    __syncthreads();
    int n = blockIdx.x * 128 + t;
    if (n >= NN) return;
    float acc[32];
#pragma unroll
    for (int u = 0; u < 32; u++) acc[u] = 0.f;
    const float4* kr = reinterpret_cast<const float4*>(g_kg + (size_t)n * DIM);
    for (int kc = 0; kc < DIM / 4; kc++) {
        float4 v = kr[kc];
#pragma unroll
        for (int u = 0; u < 32; u++)
            acc[u] += su[u][kc*4]*v.x + su[u][kc*4+1]*v.y + su[u][kc*4+2]*v.z + su[u][kc*4+3]*v.w;
    }
    float b = rb[n];
    for (int u = 0; u < 32; u++) out[(size_t)(u0 + u) * NN + n] = acc[u] + b;
}

// ---------------- host ----------------
static void* sym(const void* s) { void* p = nullptr; cudaGetSymbolAddress(&p, s); return p; }

extern "C" void kernel_launch(void* const* d_in, const int* in_sizes, int n_in,
                              void* d_out, int out_size) {
    const float* emb   = (const float*)d_in[0];
    const float* bases = (const float*)d_in[1];
    const float* comp  = (const float*)d_in[2];
    const float* root  = (const float*)d_in[3];
    const float* rbias = (const float*)d_in[4];
    const float* sth   = (const float*)d_in[5];
    const float* sbi   = (const float*)d_in[6];
    const float* kth   = (const float*)d_in[7];
    const float* kbi   = (const float*)d_in[8];
    const float* ipw   = (const float*)d_in[9];
    const float* ipb   = (const float*)d_in[10];
    const float* opw   = (const float*)d_in[11];
    const float* opb   = (const float*)d_in[12];
    const float* aha   = (const float*)d_in[13];
    const float* ahb   = (const float*)d_in[14];
    const float* aa    = (const float*)d_in[15];
    const float* ab    = (const float*)d_in[16];
    const float* recb  = (const float*)d_in[17];
    const int* esrc = (const int*)d_in[18];
    const int* edst = (const int*)d_in[19];
    const int* ety  = (const int*)d_in[20];
    const int* snod = (const int*)d_in[21];
    const int* sedg = (const int*)d_in[22];
    const int* knod = (const int*)d_in[23];
    const int* kedg = (const int*)d_in[24];
    const int* sri  = (const int*)d_in[25];
    const int* kri  = (const int*)d_in[26];
    const int* cxi  = (const int*)d_in[27];
    float* out = (float*)d_out;

    cudaMemsetAsync(sym(g_cnt), 0, (size_t)NN * NREL * 4, 0);
    cudaMemsetAsync(sym(g_typeCnt), 0, NREL * 4, 0);
    cudaMemsetAsync(sym(g_bdegS), 0, NHYP * 4, 0);
    cudaMemsetAsync(sym(g_bdegK), 0, NHYP * 4, 0);
    cudaMemsetAsync(sym(g_ddegS), 0, (size_t)NN * 4, 0);
    cudaMemsetAsync(sym(g_ddegK), 0, (size_t)NN * 4, 0);
    cudaMemsetAsync(sym(g_efS), 0, (size_t)NHYP * DIM * 4, 0);
    cudaMemsetAsync(sym(g_efK), 0, (size_t)NHYP * DIM * 4, 0);
    cudaMemsetAsync(sym(g_flagS), 0, (size_t)NN * 4, 0);
    cudaMemsetAsync(sym(g_flagK), 0, (size_t)NN * 4, 0);

    float* kg  = (float*)sym(g_kg);
    float* xt  = (float*)sym(g_xt);

    k_W<<<(NREL * DIM * DIM + 255) / 256, 256>>>(bases, comp);
    k_count<<<(NEDGE + 255) / 256, 256>>>(edst, ety);
    k_prefix<<<1, 1>>>();
    k_sort<<<(NEDGE + 255) / 256, 256>>>(ety);

    k_gemm128<<<(NN + 127) / 128, 256>>>(emb, root, rbias, kg, NN, 0);
    k_edge_gemm<<<EDGE_TILES, 256>>>(emb, esrc, edst);

    // sess hypergraph
    k_gemm128<<<(NN + 127) / 128, 256>>>(kg, sth, nullptr, xt, NN, 0);
    k_hyper_count<<<(NP + 255) / 256, 256>>>(snod, sedg, (int*)sym(g_bdegS), (int*)sym(g_ddegS));
    k_scatter_ef<<<(NP * 32 + 255) / 256, 256>>>(snod, sedg, (float*)sym(g_efS));
    k_flag<<<(NB * LREL + 255) / 256, 256>>>(sri, (int*)sym(g_flagS), (float*)sym(g_noS));
    k_scatter_node<<<(NP * 32 + 255) / 256, 256>>>(snod, sedg, (int*)sym(g_flagS),
                                                   (float*)sym(g_efS), (int*)sym(g_bdegS),
                                                   (float*)sym(g_noS));
    // know hypergraph
    k_gemm128<<<(NN + 127) / 128, 256>>>(kg, kth, nullptr, xt, NN, 0);
    k_hyper_count<<<(NP + 255) / 256, 256>>>(knod, kedg, (int*)sym(g_bdegK), (int*)sym(g_ddegK));
    k_scatter_ef<<<(NP * 32 + 255) / 256, 256>>>(knod, kedg, (float*)sym(g_efK));
    k_flag<<<(NB * LREL + 255) / 256, 256>>>(kri, (int*)sym(g_flagK), (float*)sym(g_noK));
    k_scatter_node<<<(NP * 32 + 255) / 256, 256>>>(knod, kedg, (int*)sym(g_flagK),
                                                   (float*)sym(g_efK), (int*)sym(g_bdegK),
                                                   (float*)sym(g_noK));

    k_gather_rel<<<(NB * LKV * DIM + 255) / 256, 256>>>(sri, kri, sbi, kbi);
    k_gather_ctx<<<(NB * LCTX * DIM + 255) / 256, 256>>>(cxi);

    // MHA projections
    float* ctx = (float*)sym(g_context);
    float* rel = (float*)sym(g_related);
    k_gemm128<<<(NB * LCTX + 127) / 128, 256>>>(ctx, ipw, ipb, (float*)sym(g_qh), NB * LCTX, 1);
    k_gemm128<<<(NB * LKV + 127) / 128, 256>>>(rel, ipw + DIM * DIM, ipb + DIM,
                                               (float*)sym(g_kh), NB * LKV, 1);
    k_gemm128<<<(NB * LKV + 127) / 128, 256>>>(rel, ipw + 2 * DIM * DIM, ipb + 2 * DIM,
                                               (float*)sym(g_vh), NB * LKV, 1);
    k_mha<<<NB * NHEAD, 32>>>();
    k_gemm128<<<(NB * LCTX + 127) / 128, 256>>>((float*)sym(g_o), opw, opb,
                                                (float*)sym(g_attrel), NB * LCTX, 1);

    // his self-attn
    k_gemm128<<<(NB * LCTX + 127) / 128, 256>>>((float*)sym(g_attrel), aha, nullptr,
                                                (float*)sym(g_t1), NB * LCTX, 0);
    k_selfattn<<<NB, 128>>>((float*)sym(g_attrel), (float*)sym(g_t1), ahb,
                            (float*)sym(g_his), LCTX);

    // user self-attn over [context, his]
    k_ucat<<<(NB * 33 * DIM + 255) / 256, 256>>>();
    k_gemm128<<<(NB * 33 + 127) / 128, 256>>>((float*)sym(g_ucat), aa, nullptr,
                                              (float*)sym(g_t2), NB * 33, 0);
    k_selfattn<<<NB, 128>>>((float*)sym(g_ucat), (float*)sym(g_t2), ab,
                            (float*)sym(g_user), 33);

    // scores
    dim3 sg((NN + 127) / 128, 2);
    k_scores<<<sg, 128>>>(recb, out);
}

// round 5
// speedup vs baseline: 1.7951x; 1.4329x over previous
#include <cuda_runtime.h>
#include <math.h>

#define NN 100000
#define DIM 128
#define NREL 12
#define NBASES 8
#define NEDGE 1000000
#define NP 400000
#define NHYP 20000
#define NB 64
#define LREL 64
#define LKV 128
#define LCTX 32
#define NHEAD 8
#define HDIM 16
#define EDGE_TILES 7830

__device__ __forceinline__ void red_add_v4(float* p, float x, float y, float z, float w) {
    asm volatile("red.global.add.v4.f32 [%0], {%1,%2,%3,%4};"
                 :: "l"(p), "f"(x), "f"(y), "f"(z), "f"(w) : "memory");
}
__device__ __forceinline__ void red_add_v2(float* p, float x, float y) {
    asm volatile("red.global.add.v2.f32 [%0], {%1,%2};"
                 :: "l"(p), "f"(x), "f"(y) : "memory");
}

// split fp32 into tf32 hi + tf32 lo (3xTF32 scheme)
__device__ __forceinline__ void split_tf32(float x, unsigned& hi, unsigned& lo) {
    unsigned h, l;
    asm("cvt.rna.tf32.f32 %0, %1;" : "=r"(h) : "f"(x));
    float lf = x - __uint_as_float(h);
    asm("cvt.rna.tf32.f32 %0, %1;" : "=r"(l) : "f"(lf));
    hi = h; lo = l;
}

__device__ __forceinline__ void mma8(float* c, const unsigned* a, const unsigned* b) {
    asm("mma.sync.aligned.m16n8k8.row.col.f32.tf32.tf32.f32 "
        "{%0,%1,%2,%3}, {%4,%5,%6,%7}, {%8,%9}, {%0,%1,%2,%3};"
        : "+f"(c[0]), "+f"(c[1]), "+f"(c[2]), "+f"(c[3])
        : "r"(a[0]), "r"(a[1]), "r"(a[2]), "r"(a[3]), "r"(b[0]), "r"(b[1]));
}

// one 32-deep K chunk: acc[2][8][4] covers 32 rows x 64 cols per warp
__device__ __forceinline__ void tc_chunk(const float (*As)[36], const float (*Bs)[136],
                                         float acc[2][8][4], int lane, int m0, int n0) {
    const int gr = lane >> 2, tg = lane & 3;
#pragma unroll
    for (int k8 = 0; k8 < 4; k8++) {
        const int kb = k8 * 8;
        unsigned bh[8][2], bl[8][2];
#pragma unroll
        for (int ns = 0; ns < 8; ns++) {
            int c = n0 + ns * 8 + gr;
            split_tf32(Bs[kb + tg][c],     bh[ns][0], bl[ns][0]);
            split_tf32(Bs[kb + tg + 4][c], bh[ns][1], bl[ns][1]);
        }
#pragma unroll
        for (int ms = 0; ms < 2; ms++) {
            int r0 = m0 + ms * 16 + gr;
            unsigned ah[4], al[4];
            split_tf32(As[r0][kb + tg],         ah[0], al[0]);
            split_tf32(As[r0 + 8][kb + tg],     ah[1], al[1]);
            split_tf32(As[r0][kb + tg + 4],     ah[2], al[2]);
            split_tf32(As[r0 + 8][kb + tg + 4], ah[3], al[3]);
#pragma unroll
            for (int ns = 0; ns < 8; ns++) {
                mma8(acc[ms][ns], ah, bh[ns]);
                mma8(acc[ms][ns], ah, bl[ns]);
                mma8(acc[ms][ns], al, bh[ns]);
            }
        }
    }
}

// ---------------- device scratch ----------------
__device__ float g_W[NREL * DIM * DIM];
__device__ float g_kg[NN * DIM];
__device__ int   g_cnt[NN * NREL];
__device__ int   g_typeCnt[NREL];
__device__ int   g_typeOff[NREL + 1];
__device__ int   g_tileOff[NREL + 1];
__device__ int   g_cursor[NREL];
__device__ int   g_sorted[NEDGE];
__device__ float g_xt[NN * DIM];
__device__ int   g_bdegS[NHYP], g_bdegK[NHYP];
__device__ int   g_ddegS[NN], g_ddegK[NN];
__device__ float g_efS[NHYP * DIM], g_efK[NHYP * DIM];
__device__ int   g_flagS[NN], g_flagK[NN];
__device__ float g_noS[NN * DIM], g_noK[NN * DIM];
__device__ float g_related[NB * LKV * DIM];
__device__ float g_context[NB * LCTX * DIM];
__device__ float g_qh[NB * LCTX * DIM];
__device__ float g_kh[NB * LKV * DIM];
__device__ float g_vh[NB * LKV * DIM];
__device__ float g_o[NB * LCTX * DIM];
__device__ float g_attrel[NB * LCTX * DIM];
__device__ float g_t1[NB * LCTX * DIM];
__device__ float g_ucat[NB * 33 * DIM];
__device__ float g_t2[NB * 33 * DIM];
__device__ float g_his[NB * DIM];
__device__ float g_user[NB * DIM];

// ---------------- RGCN prep ----------------
__global__ void k_W(const float* __restrict__ bases, const float* __restrict__ comp) {
    int i = blockIdx.x * blockDim.x + threadIdx.x;
    if (i >= NREL * DIM * DIM) return;
    int r = i / (DIM * DIM), kn = i % (DIM * DIM);
    float s = 0.f;
#pragma unroll
    for (int b = 0; b < NBASES; b++)
        s = fmaf(comp[r * NBASES + b], bases[b * DIM * DIM + kn], s);
    g_W[i] = s;
}

__global__ void k_count(const int* __restrict__ dst, const int* __restrict__ ty) {
    __shared__ int h[NREL];
    int t = threadIdx.x;
    if (t < NREL) h[t] = 0;
    __syncthreads();
    int e = blockIdx.x * blockDim.x + t;
    if (e < NEDGE) {
        int tt = ty[e];
        atomicAdd(&g_cnt[dst[e] * NREL + tt], 1);
        atomicAdd(&h[tt], 1);
    }
    __syncthreads();
    if (t < NREL && h[t]) atomicAdd(&g_typeCnt[t], h[t]);
}

__global__ void k_prefix() {
    int off = 0, toff = 0;
    for (int r = 0; r < NREL; r++) {
        g_typeOff[r] = off; g_cursor[r] = off; g_tileOff[r] = toff;
        int c = g_typeCnt[r];
        off += c; toff += (c + 127) >> 7;
    }
    g_typeOff[NREL] = off; g_tileOff[NREL] = toff;
}

__global__ void k_sort(const int* __restrict__ ty) {
    __shared__ int h[NREL], base[NREL];
    int t = threadIdx.x;
    if (t < NREL) h[t] = 0;
    __syncthreads();
    int e = blockIdx.x * blockDim.x + t;
    int tt = -1, loc = 0;
    if (e < NEDGE) { tt = ty[e]; loc = atomicAdd(&h[tt], 1); }
    __syncthreads();
    if (t < NREL) base[t] = h[t] ? atomicAdd(&g_cursor[t], h[t]) : 0;
    __syncthreads();
    if (e < NEDGE) g_sorted[base[tt] + loc] = e;
}

// ------------- tensor-core GEMM: C[M,128] = A[M,128] @ op(B) (+bias) -------------
__global__ void __launch_bounds__(256) k_gemm128(
    const float* __restrict__ A, const float* __restrict__ Bm,
    const float* __restrict__ bias, float* __restrict__ C, int M, int transB) {
    __shared__ float As[128][36];
    __shared__ float Bs[32][136];
    const int t = threadIdx.x, lane = t & 31, warp = t >> 5;
    const int m0w = (warp & 3) * 32, n0w = (warp >> 2) * 64;
    const int blkM = blockIdx.x * 128;
    float acc[2][8][4];
#pragma unroll
    for (int i = 0; i < 2; i++)
#pragma unroll
        for (int j = 0; j < 8; j++)
#pragma unroll
            for (int q = 0; q < 4; q++) acc[i][j][q] = 0.f;
    const int mA = t >> 1, ksA = (t & 1) * 16;

    for (int k0 = 0; k0 < 128; k0 += 32) {
        int gm = blkM + mA;
        if (gm < M) {
            const float4* ap = reinterpret_cast<const float4*>(A + (size_t)gm * DIM + k0 + ksA);
#pragma unroll
            for (int q = 0; q < 4; q++) *reinterpret_cast<float4*>(&As[mA][ksA + 4 * q]) = ap[q];
        } else {
#pragma unroll
            for (int q = 0; q < 16; q++) As[mA][ksA + q] = 0.f;
        }
        if (!transB) {
            int kk = t >> 3, nc = (t & 7) * 16;
            const float4* bp = reinterpret_cast<const float4*>(Bm + (size_t)(k0 + kk) * DIM + nc);
#pragma unroll
            for (int q = 0; q < 4; q++) *reinterpret_cast<float4*>(&Bs[kk][nc + 4 * q]) = bp[q];
        } else {
            int n = t >> 1, ks = (t & 1) * 16;
            const float* bp = Bm + (size_t)n * DIM + k0 + ks;
#pragma unroll
            for (int q = 0; q < 16; q++) Bs[ks + q][n] = bp[q];
        }
        __syncthreads();
        tc_chunk(As, Bs, acc, lane, m0w, n0w);
        __syncthreads();
    }
    const int gr = lane >> 2, tg = lane & 3;
#pragma unroll
    for (int ms = 0; ms < 2; ms++) {
#pragma unroll
        for (int half = 0; half < 2; half++) {
            int gm = blkM + m0w + ms * 16 + gr + half * 8;
            if (gm < M) {
                float* cp = C + (size_t)gm * DIM;
#pragma unroll
                for (int ns = 0; ns < 8; ns++) {
                    int col = n0w + ns * 8 + 2 * tg;
                    float b0 = bias ? bias[col] : 0.f;
                    float b1 = bias ? bias[col + 1] : 0.f;
                    float2 v = make_float2(acc[ms][ns][half * 2] + b0,
                                           acc[ms][ns][half * 2 + 1] + b1);
                    *reinterpret_cast<float2*>(cp + col) = v;
                }
            }
        }
    }
}

// ------------- RGCN edge GEMM (tensor core): kg[dst] += norm * x[src] @ W[type] -------------
__global__ void __launch_bounds__(256) k_edge_gemm(
    const float* __restrict__ X, const int* __restrict__ esrc, const int* __restrict__ edst) {
    __shared__ float As[128][36];
    __shared__ float Bs[32][136];
    __shared__ int   sSrc[128], sDst[128];
    __shared__ float sNorm[128];
    const int bid = blockIdx.x;
    if (bid >= g_tileOff[NREL]) return;
    int r = 0;
    while (bid >= g_tileOff[r + 1]) r++;
    const int base = g_typeOff[r] + (bid - g_tileOff[r]) * 128;
    int cnt = g_typeOff[r + 1] - base;
    if (cnt > 128) cnt = 128;
    const int t = threadIdx.x, lane = t & 31, warp = t >> 5;
    const int m0w = (warp & 3) * 32, n0w = (warp >> 2) * 64;
    if (t < 128) {
        if (t < cnt) {
            int e = g_sorted[base + t];
            int d = edst[e];
            sSrc[t] = esrc[e]; sDst[t] = d;
            sNorm[t] = 1.0f / fmaxf((float)g_cnt[d * NREL + r], 1.0f);
        } else { sSrc[t] = 0; sDst[t] = -1; sNorm[t] = 0.f; }
    }
    __syncthreads();
    float acc[2][8][4];
#pragma unroll
    for (int i = 0; i < 2; i++)
#pragma unroll
        for (int j = 0; j < 8; j++)
#pragma unroll
            for (int q = 0; q < 4; q++) acc[i][j][q] = 0.f;
    const int mA = t >> 1, ksA = (t & 1) * 16;
    const float* Wr = g_W + (size_t)r * DIM * DIM;

    for (int k0 = 0; k0 < 128; k0 += 32) {
        {
            float nrm = sNorm[mA];
            const float4* ap = reinterpret_cast<const float4*>(X + (size_t)sSrc[mA] * DIM + k0 + ksA);
#pragma unroll
            for (int q = 0; q < 4; q++) {
                float4 v = ap[q];
                v.x *= nrm; v.y *= nrm; v.z *= nrm; v.w *= nrm;
                *reinterpret_cast<float4*>(&As[mA][ksA + 4 * q]) = v;
            }
        }
        {
            int kk = t >> 3, nc = (t & 7) * 16;
            const float4* bp = reinterpret_cast<const float4*>(Wr + (size_t)(k0 + kk) * DIM + nc);
#pragma unroll
            for (int q = 0; q < 4; q++) *reinterpret_cast<float4*>(&Bs[kk][nc + 4 * q]) = bp[q];
        }
        __syncthreads();
        tc_chunk(As, Bs, acc, lane, m0w, n0w);
        __syncthreads();
    }
    const int gr = lane >> 2, tg = lane & 3;
#pragma unroll
    for (int ms = 0; ms < 2; ms++) {
#pragma unroll
        for (int half = 0; half < 2; half++) {
            int rr = m0w + ms * 16 + gr + half * 8;
            int dn = sDst[rr];
            if (dn >= 0) {
                float* op = g_kg + (size_t)dn * DIM;
#pragma unroll
                for (int ns = 0; ns < 8; ns++) {
                    int col = n0w + ns * 8 + 2 * tg;
                    red_add_v2(op + col, acc[ms][ns][half * 2], acc[ms][ns][half * 2 + 1]);
                }
            }
        }
    }
}

// ---------------- hypergraph ----------------
__global__ void k_hyper_count(const int* __restrict__ nodes, const int* __restrict__ edges,
                              int* __restrict__ bdeg, int* __restrict__ ddeg) {
    int p = blockIdx.x * blockDim.x + threadIdx.x;
    if (p >= NP) return;
    atomicAdd(&bdeg[edges[p]], 1);
    atomicAdd(&ddeg[nodes[p]], 1);
}

__global__ void k_scatter_ef(const int* __restrict__ nodes, const int* __restrict__ edges,
                             float* __restrict__ ef) {
    int w = (blockIdx.x * blockDim.x + threadIdx.x) >> 5;
    int lane = threadIdx.x & 31;
    if (w >= NP) return;
    float4 v = *reinterpret_cast<const float4*>(&g_xt[(size_t)nodes[w] * DIM + lane * 4]);
    red_add_v4(ef + (size_t)edges[w] * DIM + lane * 4, v.x, v.y, v.z, v.w);
}

__global__ void k_flag(const int* __restrict__ idx, int* __restrict__ flag, float* __restrict__ no) {
    int i = blockIdx.x * blockDim.x + threadIdx.x;
    if (i >= NB * LREL) return;
    int n = idx[i];
    flag[n] = 1;
    float* p = no + (size_t)n * DIM;
    for (int d = 0; d < DIM; d++) p[d] = 0.f;
}

__global__ void k_scatter_node(const int* __restrict__ nodes, const int* __restrict__ edges,
                               const int* __restrict__ flag, const float* __restrict__ ef,
                               const int* __restrict__ bdeg, float* __restrict__ no) {
    int w = (blockIdx.x * blockDim.x + threadIdx.x) >> 5;
    int lane = threadIdx.x & 31;
    if (w >= NP) return;
    int n = nodes[w];
    if (!flag[n]) return;
    int he = edges[w];
    int d = bdeg[he];
    float inv = (d > 0) ? (1.0f / (float)d) : 0.0f;
    float4 v = *reinterpret_cast<const float4*>(ef + (size_t)he * DIM + lane * 4);
    red_add_v4(no + (size_t)n * DIM + lane * 4, v.x * inv, v.y * inv, v.z * inv, v.w * inv);
}

__global__ void k_gather_rel(const int* __restrict__ sidx, const int* __restrict__ kidx,
                             const float* __restrict__ biasS, const float* __restrict__ biasK) {
    int i = blockIdx.x * blockDim.x + threadIdx.x;
    if (i >= NB * LKV * DIM) return;
    int d = i & 127, l = (i >> 7) & 127, b = i >> 14;
    float v;
    if (l < LREL) {
        int n = sidx[b * LREL + l]; int dd = g_ddegS[n];
        v = g_noS[(size_t)n * DIM + d] * (dd > 0 ? 1.f / dd : 0.f) + biasS[d];
    } else {
        int n = kidx[b * LREL + l - LREL]; int dd = g_ddegK[n];
        v = g_noK[(size_t)n * DIM + d] * (dd > 0 ? 1.f / dd : 0.f) + biasK[d];
    }
    g_related[i] = v;
}

__global__ void k_gather_ctx(const int* __restrict__ idx) {
    int i = blockIdx.x * blockDim.x + threadIdx.x;
    if (i >= NB * LCTX * DIM) return;
    g_context[i] = g_kg[(size_t)idx[i >> 7] * DIM + (i & 127)];
}

// ---------------- attention ----------------
__global__ void k_mha() {
    int b = blockIdx.x / NHEAD, h = blockIdx.x % NHEAD;
    __shared__ float ks[LKV][HDIM], vs[LKV][HDIM];
    int t = threadIdx.x;
    for (int i = t; i < LKV * HDIM; i += 32) {
        int k = i / HDIM, d = i % HDIM;
        size_t off = ((size_t)b * LKV + k) * DIM + h * HDIM + d;
        ks[k][d] = g_kh[off]; vs[k][d] = g_vh[off];
    }
    __syncwarp();
    float q[HDIM];
    size_t qoff = ((size_t)b * LCTX + t) * DIM + h * HDIM;
#pragma unroll
    for (int d = 0; d < HDIM; d++) q[d] = g_qh[qoff + d];
    float lg[LKV], mx = -1e30f;
    for (int k = 0; k < LKV; k++) {
        float s = 0.f;
#pragma unroll
        for (int d = 0; d < HDIM; d++) s += q[d] * ks[k][d];
        s *= 0.25f; lg[k] = s; mx = fmaxf(mx, s);
    }
    float sum = 0.f;
    for (int k = 0; k < LKV; k++) { lg[k] = expf(lg[k] - mx); sum += lg[k]; }
    float inv = 1.f / sum;
    float acc[HDIM];
#pragma unroll
    for (int d = 0; d < HDIM; d++) acc[d] = 0.f;
    for (int k = 0; k < LKV; k++) {
        float w = lg[k];
#pragma unroll
        for (int d = 0; d < HDIM; d++) acc[d] += w * vs[k][d];
    }
#pragma unroll
    for (int d = 0; d < HDIM; d++) g_o[qoff + d] = acc[d] * inv;
}

__global__ void k_selfattn(const float* __restrict__ h, const float* __restrict__ t1,
                           const float* __restrict__ bvec, float* __restrict__ out, int L) {
    int b = blockIdx.x, t = threadIdx.x;
    __shared__ float w[40];
    if (t < L) {
        float e = 0.f;
        const float* tp = t1 + ((size_t)b * L + t) * DIM;
        for (int d = 0; d < DIM; d++) e += tanhf(tp[d]) * bvec[d];
        w[t] = e;
    }
    __syncthreads();
    float mx = -1e30f;
    for (int l = 0; l < L; l++) mx = fmaxf(mx, w[l]);
    float sum = 0.f;
    for (int l = 0; l < L; l++) sum += expf(w[l] - mx);
    float inv = 1.f / sum, acc = 0.f;
    for (int l = 0; l < L; l++) acc += expf(w[l] - mx) * h[((size_t)b * L + l) * DIM + t];
    out[(size_t)b * DIM + t] = acc * inv;
}

__global__ void k_ucat() {
    int i = blockIdx.x * blockDim.x + threadIdx.x;
    if (i >= NB * 33 * DIM) return;
    int d = i & 127, l = (i >> 7) % 33, b = i / (33 * DIM);
    g_ucat[i] = (l < 32) ? g_context[((size_t)b * 32 + l) * DIM + d] : g_his[(size_t)b * DIM + d];
}

__global__ void k_scores(const float* __restrict__ rb, float* __restrict__ out) {
    __shared__ float su[32][DIM];
    int t = threadIdx.x;
    int u0 = blockIdx.y * 32;
    for (int i = t; i < 32 * DIM; i += 128)
        su[i >> 7][i & 127] = g_user[(size_t)(u0 + (i >> 7)) * DIM + (i & 127)];
    __syncthreads();
    int n = blockIdx.x * 128 + t;
    if (n >= NN) return;
    float acc[32];
#pragma unroll
    for (int u = 0; u < 32; u++) acc[u] = 0.f;
    const float4* kr = reinterpret_cast<const float4*>(g_kg + (size_t)n * DIM);
    for (int kc = 0; kc < DIM / 4; kc++) {
        float4 v = kr[kc];
#pragma unroll
        for (int u = 0; u < 32; u++)
            acc[u] += su[u][kc*4]*v.x + su[u][kc*4+1]*v.y + su[u][kc*4+2]*v.z + su[u][kc*4+3]*v.w;
    }
    float b = rb[n];
    for (int u = 0; u < 32; u++) out[(size_t)(u0 + u) * NN + n] = acc[u] + b;
}

// ---------------- host ----------------
static void* sym(const void* s) { void* p = nullptr; cudaGetSymbolAddress(&p, s); return p; }

extern "C" void kernel_launch(void* const* d_in, const int* in_sizes, int n_in,
                              void* d_out, int out_size) {
    const float* emb   = (const float*)d_in[0];
    const float* bases = (const float*)d_in[1];
    const float* comp  = (const float*)d_in[2];
    const float* root  = (const float*)d_in[3];
    const float* rbias = (const float*)d_in[4];
    const float* sth   = (const float*)d_in[5];
    const float* sbi   = (const float*)d_in[6];
    const float* kth   = (const float*)d_in[7];
    const float* kbi   = (const float*)d_in[8];
    const float* ipw   = (const float*)d_in[9];
    const float* ipb   = (const float*)d_in[10];
    const float* opw   = (const float*)d_in[11];
    const float* opb   = (const float*)d_in[12];
    const float* aha   = (const float*)d_in[13];
    const float* ahb   = (const float*)d_in[14];
    const float* aa    = (const float*)d_in[15];
    const float* ab    = (const float*)d_in[16];
    const float* recb  = (const float*)d_in[17];
    const int* esrc = (const int*)d_in[18];
    const int* edst = (const int*)d_in[19];
    const int* ety  = (const int*)d_in[20];
    const int* snod = (const int*)d_in[21];
    const int* sedg = (const int*)d_in[22];
    const int* knod = (const int*)d_in[23];
    const int* kedg = (const int*)d_in[24];
    const int* sri  = (const int*)d_in[25];
    const int* kri  = (const int*)d_in[26];
    const int* cxi  = (const int*)d_in[27];
    float* out = (float*)d_out;

    cudaMemsetAsync(sym(g_cnt), 0, (size_t)NN * NREL * 4, 0);
    cudaMemsetAsync(sym(g_typeCnt), 0, NREL * 4, 0);
    cudaMemsetAsync(sym(g_bdegS), 0, NHYP * 4, 0);
    cudaMemsetAsync(sym(g_bdegK), 0, NHYP * 4, 0);
    cudaMemsetAsync(sym(g_ddegS), 0, (size_t)NN * 4, 0);
    cudaMemsetAsync(sym(g_ddegK), 0, (size_t)NN * 4, 0);
    cudaMemsetAsync(sym(g_efS), 0, (size_t)NHYP * DIM * 4, 0);
    cudaMemsetAsync(sym(g_efK), 0, (size_t)NHYP * DIM * 4, 0);
    cudaMemsetAsync(sym(g_flagS), 0, (size_t)NN * 4, 0);
    cudaMemsetAsync(sym(g_flagK), 0, (size_t)NN * 4, 0);

    float* kg  = (float*)sym(g_kg);
    float* xt  = (float*)sym(g_xt);

    k_W<<<(NREL * DIM * DIM + 255) / 256, 256>>>(bases, comp);
    k_count<<<(NEDGE + 255) / 256, 256>>>(edst, ety);
    k_prefix<<<1, 1>>>();
    k_sort<<<(NEDGE + 255) / 256, 256>>>(ety);

    k_gemm128<<<(NN + 127) / 128, 256>>>(emb, root, rbias, kg, NN, 0);
    k_edge_gemm<<<EDGE_TILES, 256>>>(emb, esrc, edst);

    // sess hypergraph
    k_gemm128<<<(NN + 127) / 128, 256>>>(kg, sth, nullptr, xt, NN, 0);
    k_hyper_count<<<(NP + 255) / 256, 256>>>(snod, sedg, (int*)sym(g_bdegS), (int*)sym(g_ddegS));
    k_scatter_ef<<<(NP * 32 + 255) / 256, 256>>>(snod, sedg, (float*)sym(g_efS));
    k_flag<<<(NB * LREL + 255) / 256, 256>>>(sri, (int*)sym(g_flagS), (float*)sym(g_noS));
    k_scatter_node<<<(NP * 32 + 255) / 256, 256>>>(snod, sedg, (int*)sym(g_flagS),
                                                   (float*)sym(g_efS), (int*)sym(g_bdegS),
                                                   (float*)sym(g_noS));
    // know hypergraph
    k_gemm128<<<(NN + 127) / 128, 256>>>(kg, kth, nullptr, xt, NN, 0);
    k_hyper_count<<<(NP + 255) / 256, 256>>>(knod, kedg, (int*)sym(g_bdegK), (int*)sym(g_ddegK));
    k_scatter_ef<<<(NP * 32 + 255) / 256, 256>>>(knod, kedg, (float*)sym(g_efK));
    k_flag<<<(NB * LREL + 255) / 256, 256>>>(kri, (int*)sym(g_flagK), (float*)sym(g_noK));
    k_scatter_node<<<(NP * 32 + 255) / 256, 256>>>(knod, kedg, (int*)sym(g_flagK),
                                                   (float*)sym(g_efK), (int*)sym(g_bdegK),
                                                   (float*)sym(g_noK));

    k_gather_rel<<<(NB * LKV * DIM + 255) / 256, 256>>>(sri, kri, sbi, kbi);
    k_gather_ctx<<<(NB * LCTX * DIM + 255) / 256, 256>>>(cxi);

    // MHA projections
    float* ctx = (float*)sym(g_context);
    float* rel = (float*)sym(g_related);
    k_gemm128<<<(NB * LCTX + 127) / 128, 256>>>(ctx, ipw, ipb, (float*)sym(g_qh), NB * LCTX, 1);
    k_gemm128<<<(NB * LKV + 127) / 128, 256>>>(rel, ipw + DIM * DIM, ipb + DIM,
                                               (float*)sym(g_kh), NB * LKV, 1);
    k_gemm128<<<(NB * LKV + 127) / 128, 256>>>(rel, ipw + 2 * DIM * DIM, ipb + 2 * DIM,
                                               (float*)sym(g_vh), NB * LKV, 1);
    k_mha<<<NB * NHEAD, 32>>>();
    k_gemm128<<<(NB * LCTX + 127) / 128, 256>>>((float*)sym(g_o), opw, opb,
                                                (float*)sym(g_attrel), NB * LCTX, 1);

    // his self-attn
    k_gemm128<<<(NB * LCTX + 127) / 128, 256>>>((float*)sym(g_attrel), aha, nullptr,
                                                (float*)sym(g_t1), NB * LCTX, 0);
    k_selfattn<<<NB, 128>>>((float*)sym(g_attrel), (float*)sym(g_t1), ahb,
                            (float*)sym(g_his), LCTX);

    // user self-attn over [context, his]
    k_ucat<<<(NB * 33 * DIM + 255) / 256, 256>>>();
    k_gemm128<<<(NB * 33 + 127) / 128, 256>>>((float*)sym(g_ucat), aa, nullptr,
                                              (float*)sym(g_t2), NB * 33, 0);
    k_selfattn<<<NB, 128>>>((float*)sym(g_ucat), (float*)sym(g_t2), ab,
                            (float*)sym(g_user), 33);

    // scores
    dim3 sg((NN + 127) / 128, 2);
    k_scores<<<sg, 128>>>(recb, out);
}